// round 9
// baseline (speedup 1.0000x reference)
#include <cuda_runtime.h>
#include <cstdint>
#include <math.h>

#define EMBED 512
#define HID   1024
#define GATE  4096
#define BATCH 64
#define SEQ   256
#define MROWS (SEQ*BATCH)   // 16384
#define NB    128           // persistent grid size (1 CTA/SM, all resident)

#define WS_STR 1032         // ws row stride (floats); 1032 % 32 == 8 -> conflict-free LDS.64
#define PB_ROW 40           // partial-buffer row stride; 40 % 32 == 8 -> conflict-free
#define PB_W   (64*PB_ROW)  // per-warp partial region (floats)

// Scratch (static device allocations — permitted; no runtime alloc).
__device__ float g_Xg[(size_t)MROWS * GATE];    // [T][B][4H] input projection + biases
__device__ float g_Hall[(size_t)MROWS * HID];   // [T][B][H] all hidden states (full fp32)
__device__ float g_hbuf[2][BATCH * HID];        // double-buffered h (tf32-rounded)
__device__ unsigned int g_bar_count;
__device__ unsigned int g_bar_gen;

__device__ __forceinline__ float tf32r(float x) {
    asm("cvt.rna.tf32.f32 %0, %0;" : "+f"(x));
    return x;
}
__device__ __forceinline__ float4 tf32r4(float4 v) {
    v.x = tf32r(v.x); v.y = tf32r(v.y); v.z = tf32r(v.z); v.w = tf32r(v.w);
    return v;
}
// K-permuted tf32 MMA: lane k-pair is (2tg, 2tg+1) instead of (tg, tg+4).
// Exact as long as A and B use the same permutation (K is a reduction dim).
__device__ __forceinline__ void mma8(float* c, const uint32_t* a, const uint32_t* b) {
    asm volatile("mma.sync.aligned.m16n8k8.row.col.f32.tf32.tf32.f32 "
                 "{%0,%1,%2,%3}, {%4,%5,%6,%7}, {%8,%9}, {%0,%1,%2,%3};"
                 : "+f"(c[0]), "+f"(c[1]), "+f"(c[2]), "+f"(c[3])
                 : "r"(a[0]), "r"(a[1]), "r"(a[2]), "r"(a[3]), "r"(b[0]), "r"(b[1]));
}
__device__ __forceinline__ float sigm(float x) { return 1.f / (1.f + expf(-x)); }

__global__ void init_state() {
    int i = blockIdx.x * blockDim.x + threadIdx.x;
    if (i < BATCH * HID) g_hbuf[0][i] = 0.f;
    if (i == 0) { g_bar_count = 0u; g_bar_gen = 0u; }
}

// Software grid barrier: all NB CTAs co-resident (1 CTA/SM, NB=128 <= 148 SMs).
__device__ __forceinline__ void grid_bar() {
    __threadfence();
    __syncthreads();
    if (threadIdx.x == 0) {
        unsigned int gen = *(volatile unsigned int*)&g_bar_gen;
        if (atomicAdd(&g_bar_count, 1u) == NB - 1u) {
            g_bar_count = 0u;
            __threadfence();
            atomicExch(&g_bar_gen, gen + 1u);
        } else {
            while (*(volatile unsigned int*)&g_bar_gen == gen) { }
            __threadfence();
        }
    }
    __syncthreads();
}

// ---------------------------------------------------------------------------
// Generic tf32 GEMM:  C[m, n] = sum_k A[m,k] * W[n,k]  (+ bias)   (unchanged)
// ---------------------------------------------------------------------------
template<int MODE>
__launch_bounds__(256)
__global__ void gemm_tf32(const float* __restrict__ Ain,
                          const float* __restrict__ W,
                          const float* __restrict__ b1,
                          const float* __restrict__ b2,
                          float* __restrict__ Cout,
                          int K)
{
    extern __shared__ float sm[];
    float* As = sm;
    float* Bs = sm + 2 * 128 * 36;

    const float* A = (MODE == 0) ? Ain : g_Hall;
    float* C       = (MODE == 0) ? g_Xg : Cout;

    const int tid  = threadIdx.x;
    const int warp = tid >> 5, lane = tid & 31;
    const int wm = warp >> 1, wn = warp & 1;
    const int g = lane >> 2, tg = lane & 3;
    const int mBase = blockIdx.x * 128;
    const int nBase = blockIdx.y * 64;
    const int nk = K >> 5;

    float acc[2][4][4];
#pragma unroll
    for (int a = 0; a < 2; a++)
#pragma unroll
        for (int b = 0; b < 4; b++)
#pragma unroll
            for (int cc = 0; cc < 4; cc++) acc[a][b][cc] = 0.f;

    float4 ar[4], br[2];
    {
#pragma unroll
        for (int i = 0; i < 4; i++) {
            int idx = tid + i * 256;
            int r = idx >> 3, k4 = idx & 7;
            int m = mBase + r;
            size_t aoff = (MODE == 0) ? ((size_t)((m & 63) * SEQ + (m >> 6)) * EMBED)
                                      : ((size_t)m * HID);
            ar[i] = *(const float4*)(A + aoff + k4 * 4);
        }
#pragma unroll
        for (int i = 0; i < 2; i++) {
            int idx = tid + i * 256;
            int r = idx >> 3, k4 = idx & 7;
            br[i] = *(const float4*)(W + (size_t)(nBase + r) * K + k4 * 4);
        }
#pragma unroll
        for (int i = 0; i < 4; i++) {
            int idx = tid + i * 256; int r = idx >> 3, k4 = idx & 7;
            *(float4*)(As + r * 36 + k4 * 4) = tf32r4(ar[i]);
        }
#pragma unroll
        for (int i = 0; i < 2; i++) {
            int idx = tid + i * 256; int r = idx >> 3, k4 = idx & 7;
            *(float4*)(Bs + r * 36 + k4 * 4) = tf32r4(br[i]);
        }
    }
    __syncthreads();

    for (int kt = 0; kt < nk; kt++) {
        if (kt + 1 < nk) {
            const int kB = (kt + 1) * 32;
#pragma unroll
            for (int i = 0; i < 4; i++) {
                int idx = tid + i * 256;
                int r = idx >> 3, k4 = idx & 7;
                int m = mBase + r;
                size_t aoff = (MODE == 0) ? ((size_t)((m & 63) * SEQ + (m >> 6)) * EMBED)
                                          : ((size_t)m * HID);
                ar[i] = *(const float4*)(A + aoff + kB + k4 * 4);
            }
#pragma unroll
            for (int i = 0; i < 2; i++) {
                int idx = tid + i * 256;
                int r = idx >> 3, k4 = idx & 7;
                br[i] = *(const float4*)(W + (size_t)(nBase + r) * K + kB + k4 * 4);
            }
        }
        const float* as = As + (kt & 1) * (128 * 36);
        const float* bs = Bs + (kt & 1) * (64 * 36);
#pragma unroll
        for (int ks = 0; ks < 4; ks++) {
            const int kk = ks * 8;
            uint32_t af[2][4], bf[4][2];
#pragma unroll
            for (int mt = 0; mt < 2; mt++) {
                int rb = wm * 32 + mt * 16;
                af[mt][0] = __float_as_uint(as[(rb + g    ) * 36 + kk + tg    ]);
                af[mt][1] = __float_as_uint(as[(rb + g + 8) * 36 + kk + tg    ]);
                af[mt][2] = __float_as_uint(as[(rb + g    ) * 36 + kk + tg + 4]);
                af[mt][3] = __float_as_uint(as[(rb + g + 8) * 36 + kk + tg + 4]);
            }
#pragma unroll
            for (int nt = 0; nt < 4; nt++) {
                int cb = wn * 32 + nt * 8;
                bf[nt][0] = __float_as_uint(bs[(cb + g) * 36 + kk + tg    ]);
                bf[nt][1] = __float_as_uint(bs[(cb + g) * 36 + kk + tg + 4]);
            }
#pragma unroll
            for (int mt = 0; mt < 2; mt++)
#pragma unroll
                for (int nt = 0; nt < 4; nt++)
                    mma8(acc[mt][nt], af[mt], bf[nt]);
        }
        if (kt + 1 < nk) {
            float* as2 = As + ((kt + 1) & 1) * (128 * 36);
            float* bs2 = Bs + ((kt + 1) & 1) * (64 * 36);
#pragma unroll
            for (int i = 0; i < 4; i++) {
                int idx = tid + i * 256; int r = idx >> 3, k4 = idx & 7;
                *(float4*)(as2 + r * 36 + k4 * 4) = tf32r4(ar[i]);
            }
#pragma unroll
            for (int i = 0; i < 2; i++) {
                int idx = tid + i * 256; int r = idx >> 3, k4 = idx & 7;
                *(float4*)(bs2 + r * 36 + k4 * 4) = tf32r4(br[i]);
            }
        }
        __syncthreads();
    }

#pragma unroll
    for (int mt = 0; mt < 2; mt++) {
#pragma unroll
        for (int nt = 0; nt < 4; nt++) {
            int row = mBase + wm * 32 + mt * 16 + g;
            int col = nBase + wn * 32 + nt * 8 + 2 * tg;
            float bv0 = b1[col], bv1 = b1[col + 1];
            if (MODE == 0) { bv0 += b2[col]; bv1 += b2[col + 1]; }
            size_t c0off, c2off;
            if (MODE == 0) {
                c0off = (size_t)row * GATE + col;
                c2off = (size_t)(row + 8) * GATE + col;
            } else {
                c0off = (size_t)((row & 63) * SEQ + (row >> 6)) * HID + col;
                c2off = (size_t)(((row + 8) & 63) * SEQ + ((row + 8) >> 6)) * HID + col;
            }
            *(float2*)(C + c0off) = make_float2(acc[mt][nt][0] + bv0, acc[mt][nt][1] + bv1);
            *(float2*)(C + c2off) = make_float2(acc[mt][nt][2] + bv0, acc[mt][nt][3] + bv1);
        }
    }
}

// ---------------------------------------------------------------------------
// Persistent LSTM recurrence, v2:
//  - warp k-split: each of 8 warps computes the full 64x32 gate tile over a
//    K=128 slice; partials reduced via conflict-free SMEM buffer.
//  - A (h) fragments loaded DIRECTLY from global as float2 (k-permuted MMA),
//    perfectly coalesced, 4-deep software pipeline. No SMEM h staging.
//  - B (W_hh slice) resident in SMEM for all 256 steps, float2 reads.
//  - c in registers; one grid barrier per step.
// ---------------------------------------------------------------------------
__launch_bounds__(256, 1)
__global__ void lstm_persist(const float* __restrict__ Whh)
{
    extern __shared__ float sm[];
    float* ws   = sm;                  // 32 x WS_STR  (W slice, tf32)
    float* pbuf = sm + 32 * WS_STR;    // 8 x 64 x PB_ROW (partial gates)

    const int tid  = threadIdx.x;
    const int warp = tid >> 5, lane = tid & 31;   // warp = k-split index
    const int g = lane >> 2, tg = lane & 3;
    const int n0 = blockIdx.x * 8;
    const int kbase = warp * 128;

    // Stage W_hh slice ONCE: ws[j][k], j=0..31 -> gate row (j>>3)*HID + n0 + (j&7)
    for (int i = tid; i < 32 * 256; i += 256) {
        int j = i >> 8, k4 = i & 255;
        int grow = (j >> 3) * HID + n0 + (j & 7);
        float4 v = tf32r4(*(const float4*)(Whh + (size_t)grow * HID + k4 * 4));
        *(float4*)(ws + j * WS_STR + k4 * 4) = v;
    }

    // Elementwise mapping: thread owns cells (r0, j0) and (r0+32, j0).
    const int r0 = tid >> 3, j0 = tid & 7;
    const int n  = n0 + j0;
    float c0 = 0.f, c1 = 0.f;

    __syncthreads();   // ws ready (first step only needs it after this)

    for (int t = 0; t < SEQ; t++) {
        const float* __restrict__ hin  = g_hbuf[t & 1];
        float* __restrict__ hout       = g_hbuf[(t & 1) ^ 1];
        const float* __restrict__ Xgt  = g_Xg + (size_t)t * BATCH * GATE;

        // Prefetch Xg gate biases (overlap the MMA loop).
        float xi0 = Xgt[(size_t)r0 * GATE + n];
        float xf0 = Xgt[(size_t)r0 * GATE + 1024 + n];
        float xg0 = Xgt[(size_t)r0 * GATE + 2048 + n];
        float xo0 = Xgt[(size_t)r0 * GATE + 3072 + n];
        float xi1 = Xgt[(size_t)(r0 + 32) * GATE + n];
        float xf1 = Xgt[(size_t)(r0 + 32) * GATE + 1024 + n];
        float xg1 = Xgt[(size_t)(r0 + 32) * GATE + 2048 + n];
        float xo1 = Xgt[(size_t)(r0 + 32) * GATE + 3072 + n];

        float acc[16][4];
#pragma unroll
        for (int i = 0; i < 16; i++)
#pragma unroll
            for (int cc = 0; cc < 4; cc++) acc[i][cc] = 0.f;

        // A pipeline: 4-slot ring of direct global float2 fragment loads.
        float2 abuf[4][8];   // [slot][mg*2 + half]  (half: rows g / g+8)
#define LOAD_A(KC, SLOT) do {                                              \
            const int kk_ = kbase + (KC) * 8 + 2 * tg;                     \
            _Pragma("unroll")                                              \
            for (int mg = 0; mg < 4; mg++) {                               \
                abuf[SLOT][mg*2+0] = *(const float2*)(hin + (mg*16 + g    ) * HID + kk_); \
                abuf[SLOT][mg*2+1] = *(const float2*)(hin + (mg*16 + 8 + g) * HID + kk_); \
            }                                                              \
        } while (0)

        LOAD_A(0, 0); LOAD_A(1, 1); LOAD_A(2, 2);

#pragma unroll
        for (int kc = 0; kc < 16; kc++) {
            if (kc + 3 < 16) LOAD_A(kc + 3, (kc + 3) & 3);
            const int slot = kc & 3;
            const int kk = kbase + kc * 8 + 2 * tg;
            float2 bf[4];
#pragma unroll
            for (int ng = 0; ng < 4; ng++)
                bf[ng] = *(const float2*)(ws + (ng * 8 + g) * WS_STR + kk);
#pragma unroll
            for (int mg = 0; mg < 4; mg++) {
                uint32_t a[4];
                a[0] = __float_as_uint(abuf[slot][mg*2+0].x);
                a[1] = __float_as_uint(abuf[slot][mg*2+1].x);
                a[2] = __float_as_uint(abuf[slot][mg*2+0].y);
                a[3] = __float_as_uint(abuf[slot][mg*2+1].y);
#pragma unroll
                for (int ng = 0; ng < 4; ng++) {
                    uint32_t b[2];
                    b[0] = __float_as_uint(bf[ng].x);
                    b[1] = __float_as_uint(bf[ng].y);
                    mma8(acc[mg*4+ng], a, b);
                }
            }
        }
#undef LOAD_A

        // Write partials (conflict-free: PB_ROW % 32 == 8).
        {
            float* pb = pbuf + warp * PB_W;
#pragma unroll
            for (int mg = 0; mg < 4; mg++)
#pragma unroll
                for (int ng = 0; ng < 4; ng++) {
                    int base = (mg * 16 + g) * PB_ROW + ng * 8 + 2 * tg;
                    *(float2*)(pb + base) =
                        make_float2(acc[mg*4+ng][0], acc[mg*4+ng][1]);
                    *(float2*)(pb + base + 8 * PB_ROW) =
                        make_float2(acc[mg*4+ng][2], acc[mg*4+ng][3]);
                }
        }
        __syncthreads();

        // Reduce 8 partials + elementwise LSTM update (c in registers).
        {
            float iv = 0.f, fv = 0.f, gv = 0.f, ov = 0.f;
#pragma unroll
            for (int w = 0; w < 8; w++) {
                const float* pb = pbuf + w * PB_W + r0 * PB_ROW;
                iv += pb[j0];
                fv += pb[8  + j0];
                gv += pb[16 + j0];
                ov += pb[24 + j0];
            }
            iv += xi0; fv += xf0; gv += xg0; ov += xo0;
            c0 = sigm(fv) * c0 + sigm(iv) * tanhf(gv);
            float hn = sigm(ov) * tanhf(c0);
            hout[r0 * HID + n] = tf32r(hn);
            g_Hall[((size_t)t * BATCH + r0) * HID + n] = hn;

            const int r1 = r0 + 32;
            iv = fv = gv = ov = 0.f;
#pragma unroll
            for (int w = 0; w < 8; w++) {
                const float* pb = pbuf + w * PB_W + r1 * PB_ROW;
                iv += pb[j0];
                fv += pb[8  + j0];
                gv += pb[16 + j0];
                ov += pb[24 + j0];
            }
            iv += xi1; fv += xf1; gv += xg1; ov += xo1;
            c1 = sigm(fv) * c1 + sigm(iv) * tanhf(gv);
            hn = sigm(ov) * tanhf(c1);
            hout[r1 * HID + n] = tf32r(hn);
            g_Hall[((size_t)t * BATCH + r1) * HID + n] = hn;
        }

        grid_bar();   // h(t) visible everywhere; also fences pbuf reuse
    }
}

extern "C" void kernel_launch(void* const* d_in, const int* in_sizes, int n_in,
                              void* d_out, int out_size)
{
    (void)in_sizes; (void)n_in; (void)out_size;
    const float* embedded = (const float*)d_in[0];
    const float* W_ih = (const float*)d_in[1];
    const float* W_hh = (const float*)d_in[2];
    const float* b_ih = (const float*)d_in[3];
    const float* b_hh = (const float*)d_in[4];
    const float* W_fc = (const float*)d_in[5];
    const float* b_fc = (const float*)d_in[6];
    float* out = (float*)d_out;

    const int smem_gemm = (2 * 128 * 36 + 2 * 64 * 36) * 4;     // 55296 B
    const int smem_pers = (32 * WS_STR + 8 * PB_W) * 4;         // 214016 B
    cudaFuncSetAttribute(gemm_tf32<0>, cudaFuncAttributeMaxDynamicSharedMemorySize, smem_gemm);
    cudaFuncSetAttribute(gemm_tf32<1>, cudaFuncAttributeMaxDynamicSharedMemorySize, smem_gemm);
    cudaFuncSetAttribute(lstm_persist, cudaFuncAttributeMaxDynamicSharedMemorySize, smem_pers);

    // 1) zero h(0), reset grid barrier
    init_state<<<(BATCH * HID + 255) / 256, 256>>>();

    // 2) Xg[t,b,:] = embedded[b,t,:] @ W_ih^T + b_ih + b_hh
    gemm_tf32<0><<<dim3(MROWS / 128, GATE / 64), 256, smem_gemm>>>(
        embedded, W_ih, b_ih, b_hh, nullptr, EMBED);

    // 3) the whole recurrence: ONE persistent kernel
    lstm_persist<<<NB, 256, smem_pers>>>(W_hh);

    // 4) out[b,t,:] = Hall[t,b,:] @ W_fc^T + b_fc
    gemm_tf32<1><<<dim3(MROWS / 128, HID / 64), 256, smem_gemm>>>(
        nullptr, W_fc, b_fc, nullptr, out, HID);
}

// round 10
// speedup vs baseline: 1.0529x; 1.0529x over previous
#include <cuda_runtime.h>
#include <cstdint>
#include <math.h>

#define EMBED 512
#define HID   1024
#define GATE  4096
#define BATCH 64
#define SEQ   256
#define MROWS (SEQ*BATCH)   // 16384
#define NB    128           // persistent grid size (1 CTA/SM, all resident)

#define WS_STR 1032         // ws row stride (floats); %32==8 -> conflict-free LDS.64
#define PB_ROW 40           // Whh partial row stride; %32==8 -> conflict-free
#define PB_W   (64*PB_ROW)  // per-warp Whh partial region (floats)

// Scratch (static device allocations — permitted; no runtime alloc).
__device__ float g_Xg[(size_t)MROWS * GATE];    // [T][B][4H] input proj + biases
__device__ float g_hbuf[2][BATCH * HID];        // double-buffered h (tf32-rounded)
__device__ float g_Wfc[HID * HID];              // tf32-rounded W_fc
__device__ unsigned int g_flags[NB];
__device__ unsigned int g_gen;

__device__ __forceinline__ float tf32r(float x) {
    asm("cvt.rna.tf32.f32 %0, %0;" : "+f"(x));
    return x;
}
__device__ __forceinline__ float4 tf32r4(float4 v) {
    v.x = tf32r(v.x); v.y = tf32r(v.y); v.z = tf32r(v.z); v.w = tf32r(v.w);
    return v;
}
// K-permuted tf32 MMA: lane k-pair is (2tg, 2tg+1) instead of (tg, tg+4).
// Exact as long as A and B use the same permutation (K is a reduction dim).
__device__ __forceinline__ void mma8(float* c, const uint32_t* a, const uint32_t* b) {
    asm volatile("mma.sync.aligned.m16n8k8.row.col.f32.tf32.tf32.f32 "
                 "{%0,%1,%2,%3}, {%4,%5,%6,%7}, {%8,%9}, {%0,%1,%2,%3};"
                 : "+f"(c[0]), "+f"(c[1]), "+f"(c[2]), "+f"(c[3])
                 : "r"(a[0]), "r"(a[1]), "r"(a[2]), "r"(a[3]), "r"(b[0]), "r"(b[1]));
}
__device__ __forceinline__ float sigm(float x) { return 1.f / (1.f + expf(-x)); }

__device__ __forceinline__ void st_release(unsigned int* p, unsigned int v) {
    asm volatile("st.release.gpu.u32 [%0], %1;" :: "l"(p), "r"(v) : "memory");
}
__device__ __forceinline__ unsigned int ld_acquire(unsigned int* p) {
    unsigned int v;
    asm volatile("ld.acquire.gpu.u32 %0, [%1];" : "=r"(v) : "l"(p) : "memory");
    return v;
}

// prep: zero h(0), reset barrier state, tf32-round W_fc into g_Wfc.
__global__ void prep(const float* __restrict__ Wfc) {
    int i = blockIdx.x * blockDim.x + threadIdx.x;
    int stride = gridDim.x * blockDim.x;
    for (int k = i; k < HID * HID; k += stride) g_Wfc[k] = tf32r(Wfc[k]);
    if (i < BATCH * HID) g_hbuf[0][i] = 0.f;
    if (i < NB) g_flags[i] = 0u;
    if (i == 0) g_gen = 0u;
}

// ---------------------------------------------------------------------------
// Pre-GEMM:  Xg[t,b,:] = embedded[b,t,:] @ W_ih^T + (b_ih + b_hh)
// BM=128, BN=64, BK=32, 256 threads (8 warps, 4x2), warp tile 32x32. K=512.
// ---------------------------------------------------------------------------
__launch_bounds__(256)
__global__ void gemm_pre(const float* __restrict__ A,
                         const float* __restrict__ W,
                         const float* __restrict__ b1,
                         const float* __restrict__ b2)
{
    extern __shared__ float sm[];
    float* As = sm;
    float* Bs = sm + 2 * 128 * 36;
    float* C  = g_Xg;
    const int K = EMBED;

    const int tid  = threadIdx.x;
    const int warp = tid >> 5, lane = tid & 31;
    const int wm = warp >> 1, wn = warp & 1;
    const int g = lane >> 2, tg = lane & 3;
    const int mBase = blockIdx.x * 128;
    const int nBase = blockIdx.y * 64;
    const int nk = K >> 5;

    float acc[2][4][4];
#pragma unroll
    for (int a = 0; a < 2; a++)
#pragma unroll
        for (int b = 0; b < 4; b++)
#pragma unroll
            for (int cc = 0; cc < 4; cc++) acc[a][b][cc] = 0.f;

    float4 ar[4], br[2];
    {
#pragma unroll
        for (int i = 0; i < 4; i++) {
            int idx = tid + i * 256;
            int r = idx >> 3, k4 = idx & 7;
            int m = mBase + r;
            size_t aoff = (size_t)((m & 63) * SEQ + (m >> 6)) * EMBED;
            ar[i] = *(const float4*)(A + aoff + k4 * 4);
        }
#pragma unroll
        for (int i = 0; i < 2; i++) {
            int idx = tid + i * 256;
            int r = idx >> 3, k4 = idx & 7;
            br[i] = *(const float4*)(W + (size_t)(nBase + r) * K + k4 * 4);
        }
#pragma unroll
        for (int i = 0; i < 4; i++) {
            int idx = tid + i * 256; int r = idx >> 3, k4 = idx & 7;
            *(float4*)(As + r * 36 + k4 * 4) = tf32r4(ar[i]);
        }
#pragma unroll
        for (int i = 0; i < 2; i++) {
            int idx = tid + i * 256; int r = idx >> 3, k4 = idx & 7;
            *(float4*)(Bs + r * 36 + k4 * 4) = tf32r4(br[i]);
        }
    }
    __syncthreads();

    for (int kt = 0; kt < nk; kt++) {
        if (kt + 1 < nk) {
            const int kB = (kt + 1) * 32;
#pragma unroll
            for (int i = 0; i < 4; i++) {
                int idx = tid + i * 256;
                int r = idx >> 3, k4 = idx & 7;
                int m = mBase + r;
                size_t aoff = (size_t)((m & 63) * SEQ + (m >> 6)) * EMBED;
                ar[i] = *(const float4*)(A + aoff + kB + k4 * 4);
            }
#pragma unroll
            for (int i = 0; i < 2; i++) {
                int idx = tid + i * 256;
                int r = idx >> 3, k4 = idx & 7;
                br[i] = *(const float4*)(W + (size_t)(nBase + r) * K + kB + k4 * 4);
            }
        }
        const float* as = As + (kt & 1) * (128 * 36);
        const float* bs = Bs + (kt & 1) * (64 * 36);
#pragma unroll
        for (int ks = 0; ks < 4; ks++) {
            const int kk = ks * 8;
            uint32_t af[2][4], bf[4][2];
#pragma unroll
            for (int mt = 0; mt < 2; mt++) {
                int rb = wm * 32 + mt * 16;
                af[mt][0] = __float_as_uint(as[(rb + g    ) * 36 + kk + tg    ]);
                af[mt][1] = __float_as_uint(as[(rb + g + 8) * 36 + kk + tg    ]);
                af[mt][2] = __float_as_uint(as[(rb + g    ) * 36 + kk + tg + 4]);
                af[mt][3] = __float_as_uint(as[(rb + g + 8) * 36 + kk + tg + 4]);
            }
#pragma unroll
            for (int nt = 0; nt < 4; nt++) {
                int cb = wn * 32 + nt * 8;
                bf[nt][0] = __float_as_uint(bs[(cb + g) * 36 + kk + tg    ]);
                bf[nt][1] = __float_as_uint(bs[(cb + g) * 36 + kk + tg + 4]);
            }
#pragma unroll
            for (int mt = 0; mt < 2; mt++)
#pragma unroll
                for (int nt = 0; nt < 4; nt++)
                    mma8(acc[mt][nt], af[mt], bf[nt]);
        }
        if (kt + 1 < nk) {
            float* as2 = As + ((kt + 1) & 1) * (128 * 36);
            float* bs2 = Bs + ((kt + 1) & 1) * (64 * 36);
#pragma unroll
            for (int i = 0; i < 4; i++) {
                int idx = tid + i * 256; int r = idx >> 3, k4 = idx & 7;
                *(float4*)(as2 + r * 36 + k4 * 4) = tf32r4(ar[i]);
            }
#pragma unroll
            for (int i = 0; i < 2; i++) {
                int idx = tid + i * 256; int r = idx >> 3, k4 = idx & 7;
                *(float4*)(bs2 + r * 36 + k4 * 4) = tf32r4(br[i]);
            }
        }
        __syncthreads();
    }

#pragma unroll
    for (int mt = 0; mt < 2; mt++) {
#pragma unroll
        for (int nt = 0; nt < 4; nt++) {
            int row = mBase + wm * 32 + mt * 16 + g;
            int col = nBase + wn * 32 + nt * 8 + 2 * tg;
            float bv0 = b1[col] + b2[col];
            float bv1 = b1[col + 1] + b2[col + 1];
            size_t c0off = (size_t)row * GATE + col;
            size_t c2off = (size_t)(row + 8) * GATE + col;
            *(float2*)(C + c0off) = make_float2(acc[mt][nt][0] + bv0, acc[mt][nt][1] + bv1);
            *(float2*)(C + c2off) = make_float2(acc[mt][nt][2] + bv0, acc[mt][nt][3] + bv1);
        }
    }
}

// ---------------------------------------------------------------------------
// Persistent LSTM recurrence + FUSED fc projection, v3:
//  - 8-way warp k-split over K=1024; A (h) fragments direct from global
//    (k-permuted MMA, coalesced float2), pipelined 4 deep.
//  - W_hh slice (32x1024) resident in SMEM; W_fc slice (8x1024, tf32) read
//    from global each step (L2-resident) and multiplied against the SAME
//    A fragments -> out(t-1) for free in A-traffic.
//  - flag-tree grid barrier: parallel release stores + CTA0 aggregation.
//  - fc reduction/stores happen AFTER the flag release (off critical path).
// ---------------------------------------------------------------------------
__launch_bounds__(256, 1)
__global__ void lstm_persist(const float* __restrict__ Whh,
                             const float* __restrict__ b_fc,
                             float* __restrict__ out)
{
    extern __shared__ float sm[];
    float* ws   = sm;                  // 32 x WS_STR (W_hh slice, tf32)
    float* pbuf = sm + 32 * WS_STR;    // 8 x 64 x PB_ROW (Whh partials)
                                       // pbufF aliases pbuf[0 .. 8*512)

    const int tid  = threadIdx.x;
    const int warp = tid >> 5, lane = tid & 31;   // warp = k-split index
    const int g = lane >> 2, tg = lane & 3;
    const int bid = blockIdx.x;
    const int n0 = bid * 8;
    const int kbase = warp * 128;

    // Stage W_hh slice ONCE: ws[j][k], j -> gate row (j>>3)*HID + n0 + (j&7)
    for (int i = tid; i < 32 * 256; i += 256) {
        int j = i >> 8, k4 = i & 255;
        int grow = (j >> 3) * HID + n0 + (j & 7);
        float4 v = tf32r4(*(const float4*)(Whh + (size_t)grow * HID + k4 * 4));
        *(float4*)(ws + j * WS_STR + k4 * 4) = v;
    }

    // Elementwise mapping: thread owns cells (r0, j0) and (r0+32, j0).
    const int r0 = tid >> 3, j0 = tid & 7;
    const int n  = n0 + j0;
    const float bfc = b_fc[n];
    float c0 = 0.f, c1 = 0.f;

    __syncthreads();   // ws ready

    for (int t = 0; t <= SEQ; t++) {
        const float* __restrict__ hin = g_hbuf[t & 1];
        float* __restrict__ hout      = g_hbuf[(t & 1) ^ 1];

        // Prefetch Xg gate biases (overlap the MMA loop). Valid only t<SEQ.
        float xi0 = 0.f, xf0 = 0.f, xg0 = 0.f, xo0 = 0.f;
        float xi1 = 0.f, xf1 = 0.f, xg1 = 0.f, xo1 = 0.f;
        if (t < SEQ) {
            const float* __restrict__ Xgt = g_Xg + (size_t)t * BATCH * GATE;
            xi0 = Xgt[(size_t)r0 * GATE + n];
            xf0 = Xgt[(size_t)r0 * GATE + 1024 + n];
            xg0 = Xgt[(size_t)r0 * GATE + 2048 + n];
            xo0 = Xgt[(size_t)r0 * GATE + 3072 + n];
            xi1 = Xgt[(size_t)(r0 + 32) * GATE + n];
            xf1 = Xgt[(size_t)(r0 + 32) * GATE + 1024 + n];
            xg1 = Xgt[(size_t)(r0 + 32) * GATE + 2048 + n];
            xo1 = Xgt[(size_t)(r0 + 32) * GATE + 3072 + n];
        }

        float acc[16][4];   // Whh partial accumulators
        float accF[4][4];   // fc partial accumulators (out(t-1))
#pragma unroll
        for (int i = 0; i < 16; i++)
#pragma unroll
            for (int cc = 0; cc < 4; cc++) acc[i][cc] = 0.f;
#pragma unroll
        for (int i = 0; i < 4; i++)
#pragma unroll
            for (int cc = 0; cc < 4; cc++) accF[i][cc] = 0.f;

        // A pipeline: 4-slot ring of direct global float2 fragment loads.
        float2 abuf[4][8];
#define LOAD_A(KC, SLOT) do {                                              \
            const int kk_ = kbase + (KC) * 8 + 2 * tg;                     \
            _Pragma("unroll")                                              \
            for (int mg = 0; mg < 4; mg++) {                               \
                abuf[SLOT][mg*2+0] = *(const float2*)(hin + (mg*16 + g    ) * HID + kk_); \
                abuf[SLOT][mg*2+1] = *(const float2*)(hin + (mg*16 + 8 + g) * HID + kk_); \
            }                                                              \
        } while (0)

        LOAD_A(0, 0); LOAD_A(1, 1); LOAD_A(2, 2);

#pragma unroll
        for (int kc = 0; kc < 16; kc++) {
            if (kc + 3 < 16) LOAD_A(kc + 3, (kc + 3) & 3);
            const int slot = kc & 3;
            const int kk = kbase + kc * 8 + 2 * tg;
            float2 bf[4];
#pragma unroll
            for (int ng = 0; ng < 4; ng++)
                bf[ng] = *(const float2*)(ws + (ng * 8 + g) * WS_STR + kk);
            float2 wf = *(const float2*)(g_Wfc + (size_t)(n0 + g) * HID + kk);
#pragma unroll
            for (int mg = 0; mg < 4; mg++) {
                uint32_t a[4];
                a[0] = __float_as_uint(abuf[slot][mg*2+0].x);
                a[1] = __float_as_uint(abuf[slot][mg*2+1].x);
                a[2] = __float_as_uint(abuf[slot][mg*2+0].y);
                a[3] = __float_as_uint(abuf[slot][mg*2+1].y);
#pragma unroll
                for (int ng = 0; ng < 4; ng++) {
                    uint32_t b[2];
                    b[0] = __float_as_uint(bf[ng].x);
                    b[1] = __float_as_uint(bf[ng].y);
                    mma8(acc[mg*4+ng], a, b);
                }
                uint32_t bF[2];
                bF[0] = __float_as_uint(wf.x);
                bF[1] = __float_as_uint(wf.y);
                mma8(accF[mg], a, bF);
            }
        }
#undef LOAD_A

        if (t < SEQ) {
            // Whh partials (conflict-free: PB_ROW % 32 == 8).
            {
                float* pb = pbuf + warp * PB_W;
#pragma unroll
                for (int mg = 0; mg < 4; mg++)
#pragma unroll
                    for (int ng = 0; ng < 4; ng++) {
                        int base = (mg * 16 + g) * PB_ROW + ng * 8 + 2 * tg;
                        *(float2*)(pb + base) =
                            make_float2(acc[mg*4+ng][0], acc[mg*4+ng][1]);
                        *(float2*)(pb + base + 8 * PB_ROW) =
                            make_float2(acc[mg*4+ng][2], acc[mg*4+ng][3]);
                    }
            }
            __syncthreads();

            // Reduce 8 partials + elementwise LSTM update (c in registers).
            {
                float iv = 0.f, fv = 0.f, gv = 0.f, ov = 0.f;
#pragma unroll
                for (int w = 0; w < 8; w++) {
                    const float* pb = pbuf + w * PB_W + r0 * PB_ROW;
                    iv += pb[j0];
                    fv += pb[8  + j0];
                    gv += pb[16 + j0];
                    ov += pb[24 + j0];
                }
                iv += xi0; fv += xf0; gv += xg0; ov += xo0;
                c0 = sigm(fv) * c0 + sigm(iv) * tanhf(gv);
                hout[r0 * HID + n] = tf32r(sigm(ov) * tanhf(c0));

                const int r1 = r0 + 32;
                iv = fv = gv = ov = 0.f;
#pragma unroll
                for (int w = 0; w < 8; w++) {
                    const float* pb = pbuf + w * PB_W + r1 * PB_ROW;
                    iv += pb[j0];
                    fv += pb[8  + j0];
                    gv += pb[16 + j0];
                    ov += pb[24 + j0];
                }
                iv += xi1; fv += xf1; gv += xg1; ov += xo1;
                c1 = sigm(fv) * c1 + sigm(iv) * tanhf(gv);
                hout[r1 * HID + n] = tf32r(sigm(ov) * tanhf(c1));
            }
            __syncthreads();               // pbuf reads done + all h stored
            if (tid == 0) st_release(&g_flags[bid], (unsigned)(t + 1));
        } else {
            __syncthreads();               // separate prev fc reads from writes
        }

        // fc partials -> pbufF (aliases pbuf; per warp [64][8], conflict-free)
        {
            float* pf = pbuf + warp * 512;
#pragma unroll
            for (int mg = 0; mg < 4; mg++) {
                int base = (mg * 16 + g) * 8 + 2 * tg;
                *(float2*)(pf + base)      = make_float2(accF[mg][0], accF[mg][1]);
                *(float2*)(pf + base + 64) = make_float2(accF[mg][2], accF[mg][3]);
            }
        }
        __syncthreads();

        // fc reduce + store out(t-1)   [off the critical path]
        if (t > 0) {
            float fo0 = 0.f, fo1 = 0.f;
#pragma unroll
            for (int w = 0; w < 8; w++) {
                fo0 += pbuf[w * 512 + r0 * 8 + j0];
                fo1 += pbuf[w * 512 + (r0 + 32) * 8 + j0];
            }
            out[((size_t)r0        * SEQ + (t - 1)) * HID + n] = fo0 + bfc;
            out[((size_t)(r0 + 32) * SEQ + (t - 1)) * HID + n] = fo1 + bfc;
        }

        // flag-tree grid barrier (skip after final step)
        if (t < SEQ) {
            if (bid == 0) {
                if (tid < NB) {
                    while (ld_acquire(&g_flags[tid]) <= (unsigned)t) { }
                }
                __syncthreads();
                if (tid == 0) st_release(&g_gen, (unsigned)(t + 1));
            } else {
                if (tid == 0) {
                    while (ld_acquire(&g_gen) <= (unsigned)t) { }
                }
                __syncthreads();
            }
        }
    }
}

extern "C" void kernel_launch(void* const* d_in, const int* in_sizes, int n_in,
                              void* d_out, int out_size)
{
    (void)in_sizes; (void)n_in; (void)out_size;
    const float* embedded = (const float*)d_in[0];
    const float* W_ih = (const float*)d_in[1];
    const float* W_hh = (const float*)d_in[2];
    const float* b_ih = (const float*)d_in[3];
    const float* b_hh = (const float*)d_in[4];
    const float* W_fc = (const float*)d_in[5];
    const float* b_fc = (const float*)d_in[6];
    float* out = (float*)d_out;

    const int smem_gemm = (2 * 128 * 36 + 2 * 64 * 36) * 4;     // 55296 B
    const int smem_pers = (32 * WS_STR + 8 * PB_W) * 4;         // 214016 B
    cudaFuncSetAttribute(gemm_pre,     cudaFuncAttributeMaxDynamicSharedMemorySize, smem_gemm);
    cudaFuncSetAttribute(lstm_persist, cudaFuncAttributeMaxDynamicSharedMemorySize, smem_pers);

    // 1) zero h(0), reset barrier, tf32-round W_fc
    prep<<<256, 256>>>(W_fc);

    // 2) Xg[t,b,:] = embedded[b,t,:] @ W_ih^T + b_ih + b_hh
    gemm_pre<<<dim3(MROWS / 128, GATE / 64), 256, smem_gemm>>>(
        embedded, W_ih, b_ih, b_hh);

    // 3) recurrence + fused fc projection: ONE persistent kernel
    lstm_persist<<<NB, 256, smem_pers>>>(W_hh, b_fc, out);
}